// round 10
// baseline (speedup 1.0000x reference)
#include <cuda_runtime.h>
#include <cuda_bf16.h>
#include <math.h>

#define N_NODES 10000
#define E0_EDGES 100000
#define E_TOT 110000
#define IN_DIM 512
#define HID 256
#define ON_DIM 512
#define H1 4
#define H2 1
#define D1 (H1*HID)
#define D2 (H2*HID)
#define OUT_C 10
#define K_MIX 5

// ---------------- scratch (device globals; no allocation allowed) ----------------
__device__ float g_xh1[(size_t)N_NODES * H1 * ON_DIM];
__device__ float g_h1[(size_t)N_NODES * D1];
__device__ float g_xh2[(size_t)N_NODES * H2 * ON_DIM];
__device__ float g_h2[(size_t)N_NODES * D2];
__device__ float g_si[N_NODES * H1];
__device__ float g_sj[N_NODES * H1];
__device__ float g_w[(size_t)E_TOT * H1];          // fallback path only
__device__ float g_isig1[D1 * K_MIX];
__device__ float g_cterm1[D1 * K_MIX];
__device__ float g_isig2[D2 * K_MIX];
__device__ float g_cterm2[D2 * K_MIX];
__device__ int   g_degi[N_NODES];
__device__ int   g_cnt[N_NODES];
__device__ int   g_off[N_NODES + 1];
__device__ int   g_csr_src[E_TOT];
__device__ int   g_csr_eid[E_TOT];
__device__ double g_acc[4];

// ---------------- helpers ----------------
__device__ __forceinline__ void edge_sd(const int* __restrict__ ei, int e, int& s, int& d) {
    if (e < E0_EDGES) { s = ei[e]; d = ei[E0_EDGES + e]; }
    else { s = e - E0_EDGES; d = s; }
}
__device__ __forceinline__ float warpMaxAll(float v) {
    #pragma unroll
    for (int o = 16; o; o >>= 1) v = fmaxf(v, __shfl_xor_sync(0xFFFFFFFFu, v, o));
    return v;
}
__device__ __forceinline__ float warpSumAll(float v) {
    #pragma unroll
    for (int o = 16; o; o >>= 1) v += __shfl_xor_sync(0xFFFFFFFFu, v, o);
    return v;
}
__device__ __forceinline__ void blockReduceAddTo(double* target, float v) {
    #pragma unroll
    for (int o = 16; o; o >>= 1) v += __shfl_down_sync(0xFFFFFFFFu, v, o);
    __shared__ float ws[8];
    int lane = threadIdx.x & 31, w = threadIdx.x >> 5;
    if (!lane) ws[w] = v;
    __syncthreads();
    if (w == 0) {
        int nw = (blockDim.x + 31) >> 5;
        v = (lane < nw) ? ws[lane] : 0.0f;
        #pragma unroll
        for (int o = 4; o; o >>= 1) v += __shfl_down_sync(0xFFFFFFFFu, v, o);
        if (!lane) atomicAdd(target, (double)v);
    }
}
// reduce two scalars at once (single shared pass, one sync)
__device__ __forceinline__ void blockReduceAddTo2(double* t0, float v0, double* t1, float v1) {
    #pragma unroll
    for (int o = 16; o; o >>= 1) {
        v0 += __shfl_down_sync(0xFFFFFFFFu, v0, o);
        v1 += __shfl_down_sync(0xFFFFFFFFu, v1, o);
    }
    __shared__ float ws[2][8];
    int lane = threadIdx.x & 31, w = threadIdx.x >> 5;
    if (!lane) { ws[0][w] = v0; ws[1][w] = v1; }
    __syncthreads();
    if (w == 0) {
        int nw = (blockDim.x + 31) >> 5;
        v0 = (lane < nw) ? ws[0][lane] : 0.0f;
        v1 = (lane < nw) ? ws[1][lane] : 0.0f;
        #pragma unroll
        for (int o = 4; o; o >>= 1) {
            v0 += __shfl_down_sync(0xFFFFFFFFu, v0, o);
            v1 += __shfl_down_sync(0xFFFFFFFFu, v1, o);
        }
        if (!lane) { atomicAdd(t0, (double)v0); atomicAdd(t1, (double)v1); }
    }
}
__device__ __forceinline__ float to_tf32(float x) {
    float y;
    asm("cvt.rna.tf32.f32 %0, %1;" : "=f"(y) : "f"(x));
    return y;
}

// ---------------- setup kernels ----------------
__global__ void init_kernel() {
    int i = blockIdx.x * blockDim.x + threadIdx.x;
    if (i < 4) g_acc[i] = 0.0;
    if (i < N_NODES) { g_degi[i] = 0; g_cnt[i] = 0; }
}
__global__ void deg_kernel(const int* __restrict__ ei) {
    int e = blockIdx.x * blockDim.x + threadIdx.x;
    if (e >= E_TOT) return;
    int s, d; edge_sd(ei, e, s, d);
    atomicAdd(&g_degi[d], 1);
}
__global__ void scan_kernel() {
    __shared__ int wsum[32];
    __shared__ int carry;
    int tid = threadIdx.x, lane = tid & 31, wid = tid >> 5;
    if (tid == 0) carry = 0;
    __syncthreads();
    for (int base = 0; base < N_NODES; base += 1024) {
        int i = base + tid;
        int v = (i < N_NODES) ? g_degi[i] : 0;
        int x = v;
        #pragma unroll
        for (int o = 1; o < 32; o <<= 1) {
            int y = __shfl_up_sync(0xFFFFFFFFu, x, o);
            if (lane >= o) x += y;
        }
        if (lane == 31) wsum[wid] = x;
        __syncthreads();
        if (wid == 0) {
            int s = wsum[lane];
            #pragma unroll
            for (int o = 1; o < 32; o <<= 1) {
                int y = __shfl_up_sync(0xFFFFFFFFu, s, o);
                if (lane >= o) s += y;
            }
            wsum[lane] = s;
        }
        __syncthreads();
        int incl = x + (wid ? wsum[wid - 1] : 0) + carry;
        if (i < N_NODES) g_off[i] = incl - v;
        __syncthreads();
        if (tid == 1023) carry = incl;
        __syncthreads();
    }
    if (tid == 0) g_off[N_NODES] = carry;
}
__global__ void csrfill_kernel(const int* __restrict__ ei) {
    int e = blockIdx.x * blockDim.x + threadIdx.x;
    if (e >= E_TOT) return;
    int s, d; edge_sd(ei, e, s, d);
    int p = g_off[d] + atomicAdd(&g_cnt[d], 1);
    g_csr_src[p] = s;
    g_csr_eid[p] = e;
}

// ---------------- MoG parameter precompute ----------------
__global__ void prep_mog_kernel(const float* __restrict__ pi, const float* __restrict__ logsig,
                                float* __restrict__ isig, float* __restrict__ cterm, int DK) {
    __shared__ float lpi[K_MIX];
    if (threadIdx.x == 0) {
        float m = -1e30f, t[K_MIX];
        #pragma unroll
        for (int k = 0; k < K_MIX; k++) { t[k] = pi[k]; m = fmaxf(m, t[k]); }
        float se = 0.f;
        #pragma unroll
        for (int k = 0; k < K_MIX; k++) se += __expf(t[k] - m);
        float lse = m + __logf(se);
        #pragma unroll
        for (int k = 0; k < K_MIX; k++) lpi[k] = t[k] - lse;
    }
    __syncthreads();
    int i = blockIdx.x * blockDim.x + threadIdx.x;
    if (i < DK) {
        float ls = logsig[i];
        isig[i]  = __expf(-ls);
        cterm[i] = lpi[i % K_MIX] - ls;
    }
}

// ---------------- TF32 tensor-core GEMM, conflict-free smem (pad 136) ----------------
#define TK 16
#define LDP 136
__global__ __launch_bounds__(256, 2)
void tf32gemm_kernel(const float* __restrict__ A, const float* __restrict__ B,
                     float* __restrict__ C, int M, int Nn, int Kd) {
    __shared__ float As[TK][LDP];
    __shared__ float Bs[TK][LDP];
    int t = threadIdx.x;
    int lane = t & 31, w = t >> 5;
    int warpM = w & 3, warpN = w >> 2;
    int grp = lane >> 2, tig = lane & 3;
    int row0 = blockIdx.y * 128, col0 = blockIdx.x * 128;

    float c[2][8][4];
    #pragma unroll
    for (int mt = 0; mt < 2; mt++)
        #pragma unroll
        for (int nt = 0; nt < 8; nt++)
            #pragma unroll
            for (int i = 0; i < 4; i++) c[mt][nt][i] = 0.f;

    for (int k0 = 0; k0 < Kd; k0 += TK) {
        {
            int r = t >> 1, cc = (t & 1) * 8;
            float4 v0 = make_float4(0.f, 0.f, 0.f, 0.f), v1 = v0;
            if (row0 + r < M) {
                const float* ap = A + (size_t)(row0 + r) * Kd + k0 + cc;
                v0 = *(const float4*)ap;
                v1 = *(const float4*)(ap + 4);
            }
            As[cc + 0][r] = to_tf32(v0.x); As[cc + 1][r] = to_tf32(v0.y);
            As[cc + 2][r] = to_tf32(v0.z); As[cc + 3][r] = to_tf32(v0.w);
            As[cc + 4][r] = to_tf32(v1.x); As[cc + 5][r] = to_tf32(v1.y);
            As[cc + 6][r] = to_tf32(v1.z); As[cc + 7][r] = to_tf32(v1.w);
        }
        {
            int r1 = t >> 5, c1 = (t & 31) * 4;
            float4 v0 = *(const float4*)(B + (size_t)(k0 + r1) * Nn + col0 + c1);
            float4 v1 = *(const float4*)(B + (size_t)(k0 + r1 + 8) * Nn + col0 + c1);
            v0.x = to_tf32(v0.x); v0.y = to_tf32(v0.y); v0.z = to_tf32(v0.z); v0.w = to_tf32(v0.w);
            v1.x = to_tf32(v1.x); v1.y = to_tf32(v1.y); v1.z = to_tf32(v1.z); v1.w = to_tf32(v1.w);
            *(float4*)&Bs[r1][c1]     = v0;
            *(float4*)&Bs[r1 + 8][c1] = v1;
        }
        __syncthreads();
        #pragma unroll
        for (int ks = 0; ks < TK; ks += 8) {
            unsigned a[2][4], b[8][2];
            #pragma unroll
            for (int mt = 0; mt < 2; mt++) {
                int rb = warpM * 32 + mt * 16;
                a[mt][0] = __float_as_uint(As[ks + tig][rb + grp]);
                a[mt][1] = __float_as_uint(As[ks + tig][rb + grp + 8]);
                a[mt][2] = __float_as_uint(As[ks + tig + 4][rb + grp]);
                a[mt][3] = __float_as_uint(As[ks + tig + 4][rb + grp + 8]);
            }
            #pragma unroll
            for (int nt = 0; nt < 8; nt++) {
                int cb = warpN * 64 + nt * 8;
                b[nt][0] = __float_as_uint(Bs[ks + tig][cb + grp]);
                b[nt][1] = __float_as_uint(Bs[ks + tig + 4][cb + grp]);
            }
            #pragma unroll
            for (int mt = 0; mt < 2; mt++)
                #pragma unroll
                for (int nt = 0; nt < 8; nt++) {
                    asm volatile(
                        "mma.sync.aligned.m16n8k8.row.col.f32.tf32.tf32.f32 "
                        "{%0,%1,%2,%3}, {%4,%5,%6,%7}, {%8,%9}, {%0,%1,%2,%3};"
                        : "+f"(c[mt][nt][0]), "+f"(c[mt][nt][1]),
                          "+f"(c[mt][nt][2]), "+f"(c[mt][nt][3])
                        : "r"(a[mt][0]), "r"(a[mt][1]), "r"(a[mt][2]), "r"(a[mt][3]),
                          "r"(b[nt][0]), "r"(b[nt][1]));
                }
        }
        __syncthreads();
    }
    #pragma unroll
    for (int mt = 0; mt < 2; mt++) {
        int r0 = row0 + warpM * 32 + mt * 16 + grp;
        #pragma unroll
        for (int nt = 0; nt < 8; nt++) {
            int cc = col0 + warpN * 64 + nt * 8 + 2 * tig;
            if (r0 < M)
                *(float2*)(C + (size_t)r0 * Nn + cc) = make_float2(c[mt][nt][0], c[mt][nt][1]);
            if (r0 + 8 < M)
                *(float2*)(C + (size_t)(r0 + 8) * Nn + cc) = make_float2(c[mt][nt][2], c[mt][nt][3]);
        }
    }
}

// ---------------- attention node scores (float4) ----------------
__global__ void scores_kernel(const float* __restrict__ xh, const float* __restrict__ att,
                              float* __restrict__ s_i, float* __restrict__ s_j, int H) {
    int warp = (blockIdx.x * blockDim.x + threadIdx.x) >> 5;
    int lane = threadIdx.x & 31;
    if (warp >= N_NODES * H) return;
    int n = warp / H, h = warp % H;
    const float4* xrow = (const float4*)(xh + ((size_t)n * H + h) * ON_DIM);
    const float4* al = (const float4*)(att + (size_t)h * 2 * ON_DIM);
    const float4* ar = al + (ON_DIM >> 2);
    float a = 0.f, b = 0.f;
    #pragma unroll
    for (int k = 0; k < (ON_DIM >> 2) / 32; k++) {
        int c4 = lane + k * 32;
        float4 v = xrow[c4];
        float4 x1 = al[c4];
        float4 x2 = ar[c4];
        a += v.x * x1.x + v.y * x1.y + v.z * x1.z + v.w * x1.w;
        b += v.x * x2.x + v.y * x2.y + v.z * x2.z + v.w * x2.w;
    }
    a = warpSumAll(a); b = warpSumAll(b);
    if (!lane) { s_i[n * H + h] = a; s_j[n * H + h] = b; }
}

// ---------------- FUSED attention + aggregation + reparam (warp per (node,head)) ----------------
__global__ __launch_bounds__(256)
void attn_agg_reparam_kernel(const float* __restrict__ xh,
                             const float* __restrict__ s_i, const float* __restrict__ s_j,
                             const float* __restrict__ gmb, const float* __restrict__ eps,
                             const float* __restrict__ mu,
                             const float* __restrict__ isig, const float* __restrict__ cterm,
                             float* __restrict__ hout,
                             int H, int accKl, int accIxz) {
    int wg = blockIdx.x * 8 + (threadIdx.x >> 5);
    int lane = threadIdx.x & 31;
    float klv = 0.f, local = 0.f;
    if (wg < N_NODES * H) {
        int n = wg / H, h = wg % H;
        int b = g_off[n], eN = g_off[n + 1] - b;
        float sid = s_i[n * H + h];

        int srcR = 0;
        float weight = 0.f;
        bool fast = (eN <= 32);
        if (fast) {
            bool act = lane < eN;
            float v = -1e30f, gv = 0.f;
            if (act) {
                srcR = g_csr_src[b + lane];
                v = sid + s_j[srcR * H + h];
                v = (v > 0.f) ? v : 0.2f * v;
                gv = gmb[(size_t)g_csr_eid[b + lane] * H + h];
            }
            float m1 = warpMaxAll(v);
            float ex = act ? __expf(v - m1) : 0.f;
            float s1 = warpSumAll(ex);
            float inv1 = 1.0f / (s1 + 1e-16f);
            float lprior = __logf(1.0f / (float)eN + 1e-12f);
            float a = ex * inv1;
            float l2 = -1e30f;
            if (act) {
                klv = a * (__logf(a + 1e-12f) - lprior);
                l2 = __logf(a + 1e-16f) + gv;
            }
            float m2 = warpMaxAll(l2);
            float wv = act ? __expf(l2 - m2) : 0.f;
            float s2 = warpSumAll(wv);
            weight = wv / (s2 + 1e-16f);
        } else {
            // fallback: strided passes through g_w scratch
            float m1 = -1e30f;
            for (int j = lane; j < eN; j += 32) {
                float v = sid + s_j[g_csr_src[b + j] * H + h];
                v = (v > 0.f) ? v : 0.2f * v;
                m1 = fmaxf(m1, v);
            }
            m1 = warpMaxAll(m1);
            float s1 = 0.f;
            for (int j = lane; j < eN; j += 32) {
                float v = sid + s_j[g_csr_src[b + j] * H + h];
                v = (v > 0.f) ? v : 0.2f * v;
                s1 += __expf(v - m1);
            }
            s1 = warpSumAll(s1);
            float inv1 = 1.0f / (s1 + 1e-16f);
            float lprior = __logf(1.0f / (float)eN + 1e-12f);
            float m2 = -1e30f;
            for (int j = lane; j < eN; j += 32) {
                float v = sid + s_j[g_csr_src[b + j] * H + h];
                v = (v > 0.f) ? v : 0.2f * v;
                float a = __expf(v - m1) * inv1;
                klv += a * (__logf(a + 1e-12f) - lprior);
                float l2 = __logf(a + 1e-16f) + gmb[(size_t)g_csr_eid[b + j] * H + h];
                m2 = fmaxf(m2, l2);
            }
            m2 = warpMaxAll(m2);
            float s2 = 0.f;
            for (int j = lane; j < eN; j += 32) {
                float v = sid + s_j[g_csr_src[b + j] * H + h];
                v = (v > 0.f) ? v : 0.2f * v;
                float a = __expf(v - m1) * inv1;
                float l2 = __logf(a + 1e-16f) + gmb[(size_t)g_csr_eid[b + j] * H + h];
                float wv = __expf(l2 - m2);
                g_w[(size_t)(b + j) * H + h] = wv;
                s2 += wv;
            }
            s2 = warpSumAll(s2);
            __syncwarp();
            // normalize into registers not possible (strided); use s2inv in loop below
            weight = 1.0f / (s2 + 1e-16f);   // carries s2inv in fallback
        }

        // ---- aggregation: acc[s] covers cols [s*128 + 4*lane, +4) ----
        float4 acc[4];
        #pragma unroll
        for (int s = 0; s < 4; s++) acc[s] = make_float4(0.f, 0.f, 0.f, 0.f);

        if (fast) {
            int j = 0;
            for (; j + 2 <= eN; j += 2) {
                int  sA = __shfl_sync(0xFFFFFFFFu, srcR, j);
                int  sB = __shfl_sync(0xFFFFFFFFu, srcR, j + 1);
                float wA = __shfl_sync(0xFFFFFFFFu, weight, j);
                float wB = __shfl_sync(0xFFFFFFFFu, weight, j + 1);
                const float4* rA = (const float4*)(xh + ((size_t)sA * H + h) * ON_DIM);
                const float4* rB = (const float4*)(xh + ((size_t)sB * H + h) * ON_DIM);
                float4 vA[4], vB[4];
                #pragma unroll
                for (int s = 0; s < 4; s++) vA[s] = rA[s * 32 + lane];
                #pragma unroll
                for (int s = 0; s < 4; s++) vB[s] = rB[s * 32 + lane];
                #pragma unroll
                for (int s = 0; s < 4; s++) {
                    acc[s].x += wA * vA[s].x + wB * vB[s].x;
                    acc[s].y += wA * vA[s].y + wB * vB[s].y;
                    acc[s].z += wA * vA[s].z + wB * vB[s].z;
                    acc[s].w += wA * vA[s].w + wB * vB[s].w;
                }
            }
            if (j < eN) {
                int  sA = __shfl_sync(0xFFFFFFFFu, srcR, j);
                float wA = __shfl_sync(0xFFFFFFFFu, weight, j);
                const float4* rA = (const float4*)(xh + ((size_t)sA * H + h) * ON_DIM);
                #pragma unroll
                for (int s = 0; s < 4; s++) {
                    float4 v = rA[s * 32 + lane];
                    acc[s].x += wA * v.x; acc[s].y += wA * v.y;
                    acc[s].z += wA * v.z; acc[s].w += wA * v.w;
                }
            }
        } else {
            float s2inv = weight;
            for (int j = 0; j < eN; j++) {
                int src = g_csr_src[b + j];
                float wv = g_w[(size_t)(b + j) * H + h] * s2inv;
                const float4* rp = (const float4*)(xh + ((size_t)src * H + h) * ON_DIM);
                #pragma unroll
                for (int s = 0; s < 4; s++) {
                    float4 v = rp[s * 32 + lane];
                    acc[s].x += wv * v.x; acc[s].y += wv * v.y;
                    acc[s].z += wv * v.z; acc[s].w += wv * v.w;
                }
            }
        }

        // ---- reparam: slot p (mean) pairs with slot p+2 (raw std), same lane ----
        int D = H * HID;
        #pragma unroll
        for (int p = 0; p < 2; p++) {
            float4 mean4 = acc[p];
            float4 rs4   = acc[p + 2];
            int c0 = p * 128 + 4 * lane;
            int d0 = h * HID + c0;
            float4 e4 = *(const float4*)&eps[(size_t)n * D + d0];
            const float* mp = &mean4.x;
            const float* rp2 = &rs4.x;
            const float* ep = &e4.x;
            float zr[4];
            #pragma unroll
            for (int q = 0; q < 4; q++) {
                float rs = rp2[q];
                float stdv = fmaxf(rs, 0.f) + __logf(1.0f + __expf(-fabsf(rs))) + 1e-10f;
                float e = ep[q];
                float z = mp[q] + stdv * e;
                zr[q] = z;
                int d = d0 + q;
                float best = -1e30f;
                float comp[K_MIX];
                #pragma unroll
                for (int k = 0; k < K_MIX; k++) {
                    float tt = (z - mu[d * K_MIX + k]) * isig[d * K_MIX + k];
                    comp[k] = cterm[d * K_MIX + k] - 0.5f * tt * tt;
                    best = fmaxf(best, comp[k]);
                }
                float s2 = 0.f;
                #pragma unroll
                for (int k = 0; k < K_MIX; k++) s2 += __expf(comp[k] - best);
                local += -0.5f * e * e - best - __logf(stdv * s2);
            }
            float4 o4;
            o4.x = (zr[0] > 0.f) ? zr[0] : (__expf(zr[0]) - 1.0f);
            o4.y = (zr[1] > 0.f) ? zr[1] : (__expf(zr[1]) - 1.0f);
            o4.z = (zr[2] > 0.f) ? zr[2] : (__expf(zr[2]) - 1.0f);
            o4.w = (zr[3] > 0.f) ? zr[3] : (__expf(zr[3]) - 1.0f);
            *(float4*)&hout[(size_t)n * D + d0] = o4;
        }
    }
    blockReduceAddTo2(&g_acc[accKl], klv, &g_acc[accIxz], local);
}

// ---------------- final FC ----------------
__global__ void fc_kernel(const float* __restrict__ Wfc, const float* __restrict__ bfc,
                          float* __restrict__ out) {
    int idx = blockIdx.x * blockDim.x + threadIdx.x;
    if (idx >= N_NODES * OUT_C) return;
    int n = idx / OUT_C, o = idx % OUT_C;
    float acc = bfc[o];
    const float* hr = g_h2 + (size_t)n * D2;
    #pragma unroll 8
    for (int d = 0; d < D2; d++) acc += hr[d] * Wfc[d * OUT_C + o];
    out[idx] = acc;
}

__global__ void finalize_kernel(float* out) {
    if (threadIdx.x == 0 && blockIdx.x == 0) {
        double kl  = g_acc[0] / ((double)E_TOT * H1) + g_acc[2] / ((double)E_TOT * H2);
        double ixz = g_acc[1] / (double)N_NODES + g_acc[3] / (double)N_NODES;
        out[N_NODES * OUT_C]     = (float)kl;
        out[N_NODES * OUT_C + 1] = (float)ixz;
    }
}

// ---------------- host orchestration ----------------
static inline int cdiv(long long a, int b) { return (int)((a + b - 1) / b); }

struct Aux {
    cudaStream_t s2;
    cudaEvent_t evFork, evJoin;
    Aux() {
        cudaStreamCreateWithFlags(&s2, cudaStreamNonBlocking);
        cudaEventCreateWithFlags(&evFork, cudaEventDisableTiming);
        cudaEventCreateWithFlags(&evJoin, cudaEventDisableTiming);
    }
};
static Aux& getAux() { static Aux a; return a; }

extern "C" void kernel_launch(void* const* d_in, const int* in_sizes, int n_in,
                              void* d_out, int out_size) {
    const float* x       = (const float*)d_in[0];
    const int*   ei      = (const int*)  d_in[1];
    const float* W1      = (const float*)d_in[2];
    const float* att1    = (const float*)d_in[3];
    const float* pi1     = (const float*)d_in[4];
    const float* mu1     = (const float*)d_in[5];
    const float* logsig1 = (const float*)d_in[6];
    const float* eps1    = (const float*)d_in[7];
    const float* g1      = (const float*)d_in[8];
    const float* W2      = (const float*)d_in[9];
    const float* att2    = (const float*)d_in[10];
    const float* pi2     = (const float*)d_in[11];
    const float* mu2     = (const float*)d_in[12];
    const float* logsig2 = (const float*)d_in[13];
    const float* eps2    = (const float*)d_in[14];
    const float* g2      = (const float*)d_in[15];
    const float* Wfc     = (const float*)d_in[16];
    const float* bfc     = (const float*)d_in[17];
    float* out = (float*)d_out;

    void* p;
    float *xh1, *h1, *xh2, *h2, *si, *sj, *isig1, *cterm1, *isig2, *cterm2;
    cudaGetSymbolAddress(&p, g_xh1);    xh1 = (float*)p;
    cudaGetSymbolAddress(&p, g_h1);     h1 = (float*)p;
    cudaGetSymbolAddress(&p, g_xh2);    xh2 = (float*)p;
    cudaGetSymbolAddress(&p, g_h2);     h2 = (float*)p;
    cudaGetSymbolAddress(&p, g_si);     si = (float*)p;
    cudaGetSymbolAddress(&p, g_sj);     sj = (float*)p;
    cudaGetSymbolAddress(&p, g_isig1);  isig1 = (float*)p;
    cudaGetSymbolAddress(&p, g_cterm1); cterm1 = (float*)p;
    cudaGetSymbolAddress(&p, g_isig2);  isig2 = (float*)p;
    cudaGetSymbolAddress(&p, g_cterm2); cterm2 = (float*)p;

    Aux& aux = getAux();

    // fork side stream: graph setup + MoG precompute, overlapped with GEMM1
    cudaEventRecord(aux.evFork, 0);
    cudaStreamWaitEvent(aux.s2, aux.evFork, 0);
    init_kernel<<<cdiv(N_NODES, 256), 256, 0, aux.s2>>>();
    deg_kernel<<<cdiv(E_TOT, 256), 256, 0, aux.s2>>>(ei);
    scan_kernel<<<1, 1024, 0, aux.s2>>>();
    csrfill_kernel<<<cdiv(E_TOT, 256), 256, 0, aux.s2>>>(ei);
    prep_mog_kernel<<<cdiv(D1 * K_MIX, 256), 256, 0, aux.s2>>>(pi1, logsig1, isig1, cterm1, D1 * K_MIX);
    prep_mog_kernel<<<cdiv(D2 * K_MIX, 256), 256, 0, aux.s2>>>(pi2, logsig2, isig2, cterm2, D2 * K_MIX);
    cudaEventRecord(aux.evJoin, aux.s2);

    // main stream: GEMM1 + scores1 overlap the setup
    {
        dim3 gg(H1 * ON_DIM / 128, cdiv(N_NODES, 128));
        tf32gemm_kernel<<<gg, 256>>>(x, W1, xh1, N_NODES, H1 * ON_DIM, IN_DIM);
    }
    scores_kernel<<<cdiv((long long)N_NODES * H1 * 32, 256), 256>>>(xh1, att1, si, sj, H1);
    cudaStreamWaitEvent(0, aux.evJoin, 0);

    attn_agg_reparam_kernel<<<cdiv(N_NODES * H1, 8), 256>>>(
        xh1, si, sj, g1, eps1, mu1, isig1, cterm1, h1, H1, 0, 1);

    {
        dim3 gg(H2 * ON_DIM / 128, cdiv(N_NODES, 128));
        tf32gemm_kernel<<<gg, 256>>>(h1, W2, xh2, N_NODES, H2 * ON_DIM, D1);
    }
    scores_kernel<<<cdiv((long long)N_NODES * H2 * 32, 256), 256>>>(xh2, att2, si, sj, H2);
    attn_agg_reparam_kernel<<<cdiv(N_NODES * H2, 8), 256>>>(
        xh2, si, sj, g2, eps2, mu2, isig2, cterm2, h2, H2, 2, 3);

    fc_kernel<<<cdiv(N_NODES * OUT_C, 256), 256>>>(Wfc, bfc, out);
    finalize_kernel<<<1, 32>>>(out);
}

// round 11
// speedup vs baseline: 1.0020x; 1.0020x over previous
#include <cuda_runtime.h>
#include <cuda_bf16.h>
#include <math.h>

#define N_NODES 10000
#define E0_EDGES 100000
#define E_TOT 110000
#define IN_DIM 512
#define HID 256
#define ON_DIM 512
#define H1 4
#define H2 1
#define D1 (H1*HID)
#define D2 (H2*HID)
#define OUT_C 10
#define K_MIX 5

// ---------------- scratch (device globals; no allocation allowed) ----------------
__device__ float g_xh1[(size_t)N_NODES * H1 * ON_DIM];
__device__ float g_h1[(size_t)N_NODES * D1];
__device__ float g_xh2[(size_t)N_NODES * H2 * ON_DIM];
__device__ float g_h2[(size_t)N_NODES * D2];
__device__ float g_si[N_NODES * H1];
__device__ float g_sj[N_NODES * H1];
__device__ float g_w[(size_t)E_TOT * H1];          // fallback path only
__device__ float g_isig1[D1 * K_MIX];
__device__ float g_cterm1[D1 * K_MIX];
__device__ float g_isig2[D2 * K_MIX];
__device__ float g_cterm2[D2 * K_MIX];
__device__ int   g_degi[N_NODES];
__device__ int   g_cnt[N_NODES];
__device__ int   g_off[N_NODES + 1];
__device__ int   g_csr_src[E_TOT];
__device__ int   g_csr_eid[E_TOT];
__device__ double g_acc[4];

// ---------------- helpers ----------------
__device__ __forceinline__ void edge_sd(const int* __restrict__ ei, int e, int& s, int& d) {
    if (e < E0_EDGES) { s = ei[e]; d = ei[E0_EDGES + e]; }
    else { s = e - E0_EDGES; d = s; }
}
__device__ __forceinline__ float warpMaxAll(float v) {
    #pragma unroll
    for (int o = 16; o; o >>= 1) v = fmaxf(v, __shfl_xor_sync(0xFFFFFFFFu, v, o));
    return v;
}
__device__ __forceinline__ float warpSumAll(float v) {
    #pragma unroll
    for (int o = 16; o; o >>= 1) v += __shfl_xor_sync(0xFFFFFFFFu, v, o);
    return v;
}
__device__ __forceinline__ void blockReduceAddTo(double* target, float v) {
    #pragma unroll
    for (int o = 16; o; o >>= 1) v += __shfl_down_sync(0xFFFFFFFFu, v, o);
    __shared__ float ws[8];
    int lane = threadIdx.x & 31, w = threadIdx.x >> 5;
    if (!lane) ws[w] = v;
    __syncthreads();
    if (w == 0) {
        int nw = (blockDim.x + 31) >> 5;
        v = (lane < nw) ? ws[lane] : 0.0f;
        #pragma unroll
        for (int o = 4; o; o >>= 1) v += __shfl_down_sync(0xFFFFFFFFu, v, o);
        if (!lane) atomicAdd(target, (double)v);
    }
}
// reduce two scalars at once (single shared pass, one sync)
__device__ __forceinline__ void blockReduceAddTo2(double* t0, float v0, double* t1, float v1) {
    #pragma unroll
    for (int o = 16; o; o >>= 1) {
        v0 += __shfl_down_sync(0xFFFFFFFFu, v0, o);
        v1 += __shfl_down_sync(0xFFFFFFFFu, v1, o);
    }
    __shared__ float ws[2][8];
    int lane = threadIdx.x & 31, w = threadIdx.x >> 5;
    if (!lane) { ws[0][w] = v0; ws[1][w] = v1; }
    __syncthreads();
    if (w == 0) {
        int nw = (blockDim.x + 31) >> 5;
        v0 = (lane < nw) ? ws[0][lane] : 0.0f;
        v1 = (lane < nw) ? ws[1][lane] : 0.0f;
        #pragma unroll
        for (int o = 4; o; o >>= 1) {
            v0 += __shfl_down_sync(0xFFFFFFFFu, v0, o);
            v1 += __shfl_down_sync(0xFFFFFFFFu, v1, o);
        }
        if (!lane) { atomicAdd(t0, (double)v0); atomicAdd(t1, (double)v1); }
    }
}
__device__ __forceinline__ float to_tf32(float x) {
    float y;
    asm("cvt.rna.tf32.f32 %0, %1;" : "=f"(y) : "f"(x));
    return y;
}

// ---------------- setup kernels ----------------
__global__ void init_kernel() {
    int i = blockIdx.x * blockDim.x + threadIdx.x;
    if (i < 4) g_acc[i] = 0.0;
    if (i < N_NODES) { g_degi[i] = 0; g_cnt[i] = 0; }
}
__global__ void deg_kernel(const int* __restrict__ ei) {
    int e = blockIdx.x * blockDim.x + threadIdx.x;
    if (e >= E_TOT) return;
    int s, d; edge_sd(ei, e, s, d);
    atomicAdd(&g_degi[d], 1);
}
__global__ void scan_kernel() {
    __shared__ int wsum[32];
    __shared__ int carry;
    int tid = threadIdx.x, lane = tid & 31, wid = tid >> 5;
    if (tid == 0) carry = 0;
    __syncthreads();
    for (int base = 0; base < N_NODES; base += 1024) {
        int i = base + tid;
        int v = (i < N_NODES) ? g_degi[i] : 0;
        int x = v;
        #pragma unroll
        for (int o = 1; o < 32; o <<= 1) {
            int y = __shfl_up_sync(0xFFFFFFFFu, x, o);
            if (lane >= o) x += y;
        }
        if (lane == 31) wsum[wid] = x;
        __syncthreads();
        if (wid == 0) {
            int s = wsum[lane];
            #pragma unroll
            for (int o = 1; o < 32; o <<= 1) {
                int y = __shfl_up_sync(0xFFFFFFFFu, s, o);
                if (lane >= o) s += y;
            }
            wsum[lane] = s;
        }
        __syncthreads();
        int incl = x + (wid ? wsum[wid - 1] : 0) + carry;
        if (i < N_NODES) g_off[i] = incl - v;
        __syncthreads();
        if (tid == 1023) carry = incl;
        __syncthreads();
    }
    if (tid == 0) g_off[N_NODES] = carry;
}
__global__ void csrfill_kernel(const int* __restrict__ ei) {
    int e = blockIdx.x * blockDim.x + threadIdx.x;
    if (e >= E_TOT) return;
    int s, d; edge_sd(ei, e, s, d);
    int p = g_off[d] + atomicAdd(&g_cnt[d], 1);
    g_csr_src[p] = s;
    g_csr_eid[p] = e;
}

// ---------------- MoG parameter precompute ----------------
__global__ void prep_mog_kernel(const float* __restrict__ pi, const float* __restrict__ logsig,
                                float* __restrict__ isig, float* __restrict__ cterm, int DK) {
    __shared__ float lpi[K_MIX];
    if (threadIdx.x == 0) {
        float m = -1e30f, t[K_MIX];
        #pragma unroll
        for (int k = 0; k < K_MIX; k++) { t[k] = pi[k]; m = fmaxf(m, t[k]); }
        float se = 0.f;
        #pragma unroll
        for (int k = 0; k < K_MIX; k++) se += __expf(t[k] - m);
        float lse = m + __logf(se);
        #pragma unroll
        for (int k = 0; k < K_MIX; k++) lpi[k] = t[k] - lse;
    }
    __syncthreads();
    int i = blockIdx.x * blockDim.x + threadIdx.x;
    if (i < DK) {
        float ls = logsig[i];
        isig[i]  = __expf(-ls);
        cterm[i] = lpi[i % K_MIX] - ls;
    }
}

// ---------------- TF32 tensor-core GEMM, conflict-free smem (pad 136) ----------------
#define TK 16
#define LDP 136
__global__ __launch_bounds__(256, 2)
void tf32gemm_kernel(const float* __restrict__ A, const float* __restrict__ B,
                     float* __restrict__ C, int M, int Nn, int Kd) {
    __shared__ float As[TK][LDP];
    __shared__ float Bs[TK][LDP];
    int t = threadIdx.x;
    int lane = t & 31, w = t >> 5;
    int warpM = w & 3, warpN = w >> 2;
    int grp = lane >> 2, tig = lane & 3;
    int row0 = blockIdx.y * 128, col0 = blockIdx.x * 128;

    float c[2][8][4];
    #pragma unroll
    for (int mt = 0; mt < 2; mt++)
        #pragma unroll
        for (int nt = 0; nt < 8; nt++)
            #pragma unroll
            for (int i = 0; i < 4; i++) c[mt][nt][i] = 0.f;

    for (int k0 = 0; k0 < Kd; k0 += TK) {
        {
            int r = t >> 1, cc = (t & 1) * 8;
            float4 v0 = make_float4(0.f, 0.f, 0.f, 0.f), v1 = v0;
            if (row0 + r < M) {
                const float* ap = A + (size_t)(row0 + r) * Kd + k0 + cc;
                v0 = *(const float4*)ap;
                v1 = *(const float4*)(ap + 4);
            }
            As[cc + 0][r] = to_tf32(v0.x); As[cc + 1][r] = to_tf32(v0.y);
            As[cc + 2][r] = to_tf32(v0.z); As[cc + 3][r] = to_tf32(v0.w);
            As[cc + 4][r] = to_tf32(v1.x); As[cc + 5][r] = to_tf32(v1.y);
            As[cc + 6][r] = to_tf32(v1.z); As[cc + 7][r] = to_tf32(v1.w);
        }
        {
            int r1 = t >> 5, c1 = (t & 31) * 4;
            float4 v0 = *(const float4*)(B + (size_t)(k0 + r1) * Nn + col0 + c1);
            float4 v1 = *(const float4*)(B + (size_t)(k0 + r1 + 8) * Nn + col0 + c1);
            v0.x = to_tf32(v0.x); v0.y = to_tf32(v0.y); v0.z = to_tf32(v0.z); v0.w = to_tf32(v0.w);
            v1.x = to_tf32(v1.x); v1.y = to_tf32(v1.y); v1.z = to_tf32(v1.z); v1.w = to_tf32(v1.w);
            *(float4*)&Bs[r1][c1]     = v0;
            *(float4*)&Bs[r1 + 8][c1] = v1;
        }
        __syncthreads();
        #pragma unroll
        for (int ks = 0; ks < TK; ks += 8) {
            unsigned a[2][4], b[8][2];
            #pragma unroll
            for (int mt = 0; mt < 2; mt++) {
                int rb = warpM * 32 + mt * 16;
                a[mt][0] = __float_as_uint(As[ks + tig][rb + grp]);
                a[mt][1] = __float_as_uint(As[ks + tig][rb + grp + 8]);
                a[mt][2] = __float_as_uint(As[ks + tig + 4][rb + grp]);
                a[mt][3] = __float_as_uint(As[ks + tig + 4][rb + grp + 8]);
            }
            #pragma unroll
            for (int nt = 0; nt < 8; nt++) {
                int cb = warpN * 64 + nt * 8;
                b[nt][0] = __float_as_uint(Bs[ks + tig][cb + grp]);
                b[nt][1] = __float_as_uint(Bs[ks + tig + 4][cb + grp]);
            }
            #pragma unroll
            for (int mt = 0; mt < 2; mt++)
                #pragma unroll
                for (int nt = 0; nt < 8; nt++) {
                    asm volatile(
                        "mma.sync.aligned.m16n8k8.row.col.f32.tf32.tf32.f32 "
                        "{%0,%1,%2,%3}, {%4,%5,%6,%7}, {%8,%9}, {%0,%1,%2,%3};"
                        : "+f"(c[mt][nt][0]), "+f"(c[mt][nt][1]),
                          "+f"(c[mt][nt][2]), "+f"(c[mt][nt][3])
                        : "r"(a[mt][0]), "r"(a[mt][1]), "r"(a[mt][2]), "r"(a[mt][3]),
                          "r"(b[nt][0]), "r"(b[nt][1]));
                }
        }
        __syncthreads();
    }
    #pragma unroll
    for (int mt = 0; mt < 2; mt++) {
        int r0 = row0 + warpM * 32 + mt * 16 + grp;
        #pragma unroll
        for (int nt = 0; nt < 8; nt++) {
            int cc = col0 + warpN * 64 + nt * 8 + 2 * tig;
            if (r0 < M)
                *(float2*)(C + (size_t)r0 * Nn + cc) = make_float2(c[mt][nt][0], c[mt][nt][1]);
            if (r0 + 8 < M)
                *(float2*)(C + (size_t)(r0 + 8) * Nn + cc) = make_float2(c[mt][nt][2], c[mt][nt][3]);
        }
    }
}

// ---------------- attention node scores (float4) ----------------
__global__ void scores_kernel(const float* __restrict__ xh, const float* __restrict__ att,
                              float* __restrict__ s_i, float* __restrict__ s_j, int H) {
    int warp = (blockIdx.x * blockDim.x + threadIdx.x) >> 5;
    int lane = threadIdx.x & 31;
    if (warp >= N_NODES * H) return;
    int n = warp / H, h = warp % H;
    const float4* xrow = (const float4*)(xh + ((size_t)n * H + h) * ON_DIM);
    const float4* al = (const float4*)(att + (size_t)h * 2 * ON_DIM);
    const float4* ar = al + (ON_DIM >> 2);
    float a = 0.f, b = 0.f;
    #pragma unroll
    for (int k = 0; k < (ON_DIM >> 2) / 32; k++) {
        int c4 = lane + k * 32;
        float4 v = xrow[c4];
        float4 x1 = al[c4];
        float4 x2 = ar[c4];
        a += v.x * x1.x + v.y * x1.y + v.z * x1.z + v.w * x1.w;
        b += v.x * x2.x + v.y * x2.y + v.z * x2.z + v.w * x2.w;
    }
    a = warpSumAll(a); b = warpSumAll(b);
    if (!lane) { s_i[n * H + h] = a; s_j[n * H + h] = b; }
}

// ---------------- FUSED attention + aggregation + reparam (warp per (node,head)) ----------------
__global__ __launch_bounds__(256)
void attn_agg_reparam_kernel(const float* __restrict__ xh,
                             const float* __restrict__ s_i, const float* __restrict__ s_j,
                             const float* __restrict__ gmb, const float* __restrict__ eps,
                             const float* __restrict__ mu,
                             const float* __restrict__ isig, const float* __restrict__ cterm,
                             float* __restrict__ hout,
                             int H, int accKl, int accIxz) {
    int wg = blockIdx.x * 8 + (threadIdx.x >> 5);
    int lane = threadIdx.x & 31;
    float klv = 0.f, local = 0.f;
    if (wg < N_NODES * H) {
        int n = wg / H, h = wg % H;
        int b = g_off[n], eN = g_off[n + 1] - b;
        float sid = s_i[n * H + h];

        int srcR = 0;
        float weight = 0.f;
        bool fast = (eN <= 32);
        if (fast) {
            bool act = lane < eN;
            float v = -1e30f, gv = 0.f;
            if (act) {
                srcR = g_csr_src[b + lane];
                v = sid + s_j[srcR * H + h];
                v = (v > 0.f) ? v : 0.2f * v;
                gv = gmb[(size_t)g_csr_eid[b + lane] * H + h];
            }
            float m1 = warpMaxAll(v);
            float ex = act ? __expf(v - m1) : 0.f;
            float s1 = warpSumAll(ex);
            float inv1 = 1.0f / (s1 + 1e-16f);
            float lprior = __logf(1.0f / (float)eN + 1e-12f);
            float a = ex * inv1;
            float l2 = -1e30f;
            if (act) {
                klv = a * (__logf(a + 1e-12f) - lprior);
                l2 = __logf(a + 1e-16f) + gv;
            }
            float m2 = warpMaxAll(l2);
            float wv = act ? __expf(l2 - m2) : 0.f;
            float s2 = warpSumAll(wv);
            weight = wv / (s2 + 1e-16f);
        } else {
            // fallback: strided passes through g_w scratch
            float m1 = -1e30f;
            for (int j = lane; j < eN; j += 32) {
                float v = sid + s_j[g_csr_src[b + j] * H + h];
                v = (v > 0.f) ? v : 0.2f * v;
                m1 = fmaxf(m1, v);
            }
            m1 = warpMaxAll(m1);
            float s1 = 0.f;
            for (int j = lane; j < eN; j += 32) {
                float v = sid + s_j[g_csr_src[b + j] * H + h];
                v = (v > 0.f) ? v : 0.2f * v;
                s1 += __expf(v - m1);
            }
            s1 = warpSumAll(s1);
            float inv1 = 1.0f / (s1 + 1e-16f);
            float lprior = __logf(1.0f / (float)eN + 1e-12f);
            float m2 = -1e30f;
            for (int j = lane; j < eN; j += 32) {
                float v = sid + s_j[g_csr_src[b + j] * H + h];
                v = (v > 0.f) ? v : 0.2f * v;
                float a = __expf(v - m1) * inv1;
                klv += a * (__logf(a + 1e-12f) - lprior);
                float l2 = __logf(a + 1e-16f) + gmb[(size_t)g_csr_eid[b + j] * H + h];
                m2 = fmaxf(m2, l2);
            }
            m2 = warpMaxAll(m2);
            float s2 = 0.f;
            for (int j = lane; j < eN; j += 32) {
                float v = sid + s_j[g_csr_src[b + j] * H + h];
                v = (v > 0.f) ? v : 0.2f * v;
                float a = __expf(v - m1) * inv1;
                float l2 = __logf(a + 1e-16f) + gmb[(size_t)g_csr_eid[b + j] * H + h];
                float wv = __expf(l2 - m2);
                g_w[(size_t)(b + j) * H + h] = wv;
                s2 += wv;
            }
            s2 = warpSumAll(s2);
            __syncwarp();
            // normalize into registers not possible (strided); use s2inv in loop below
            weight = 1.0f / (s2 + 1e-16f);   // carries s2inv in fallback
        }

        // ---- aggregation: acc[s] covers cols [s*128 + 4*lane, +4) ----
        float4 acc[4];
        #pragma unroll
        for (int s = 0; s < 4; s++) acc[s] = make_float4(0.f, 0.f, 0.f, 0.f);

        if (fast) {
            int j = 0;
            for (; j + 2 <= eN; j += 2) {
                int  sA = __shfl_sync(0xFFFFFFFFu, srcR, j);
                int  sB = __shfl_sync(0xFFFFFFFFu, srcR, j + 1);
                float wA = __shfl_sync(0xFFFFFFFFu, weight, j);
                float wB = __shfl_sync(0xFFFFFFFFu, weight, j + 1);
                const float4* rA = (const float4*)(xh + ((size_t)sA * H + h) * ON_DIM);
                const float4* rB = (const float4*)(xh + ((size_t)sB * H + h) * ON_DIM);
                float4 vA[4], vB[4];
                #pragma unroll
                for (int s = 0; s < 4; s++) vA[s] = rA[s * 32 + lane];
                #pragma unroll
                for (int s = 0; s < 4; s++) vB[s] = rB[s * 32 + lane];
                #pragma unroll
                for (int s = 0; s < 4; s++) {
                    acc[s].x += wA * vA[s].x + wB * vB[s].x;
                    acc[s].y += wA * vA[s].y + wB * vB[s].y;
                    acc[s].z += wA * vA[s].z + wB * vB[s].z;
                    acc[s].w += wA * vA[s].w + wB * vB[s].w;
                }
            }
            if (j < eN) {
                int  sA = __shfl_sync(0xFFFFFFFFu, srcR, j);
                float wA = __shfl_sync(0xFFFFFFFFu, weight, j);
                const float4* rA = (const float4*)(xh + ((size_t)sA * H + h) * ON_DIM);
                #pragma unroll
                for (int s = 0; s < 4; s++) {
                    float4 v = rA[s * 32 + lane];
                    acc[s].x += wA * v.x; acc[s].y += wA * v.y;
                    acc[s].z += wA * v.z; acc[s].w += wA * v.w;
                }
            }
        } else {
            float s2inv = weight;
            for (int j = 0; j < eN; j++) {
                int src = g_csr_src[b + j];
                float wv = g_w[(size_t)(b + j) * H + h] * s2inv;
                const float4* rp = (const float4*)(xh + ((size_t)src * H + h) * ON_DIM);
                #pragma unroll
                for (int s = 0; s < 4; s++) {
                    float4 v = rp[s * 32 + lane];
                    acc[s].x += wv * v.x; acc[s].y += wv * v.y;
                    acc[s].z += wv * v.z; acc[s].w += wv * v.w;
                }
            }
        }

        // ---- reparam: slot p (mean) pairs with slot p+2 (raw std), same lane ----
        int D = H * HID;
        #pragma unroll
        for (int p = 0; p < 2; p++) {
            float4 mean4 = acc[p];
            float4 rs4   = acc[p + 2];
            int c0 = p * 128 + 4 * lane;
            int d0 = h * HID + c0;
            float4 e4 = *(const float4*)&eps[(size_t)n * D + d0];
            const float* mp = &mean4.x;
            const float* rp2 = &rs4.x;
            const float* ep = &e4.x;
            float zr[4];
            #pragma unroll
            for (int q = 0; q < 4; q++) {
                float rs = rp2[q];
                float stdv = fmaxf(rs, 0.f) + __logf(1.0f + __expf(-fabsf(rs))) + 1e-10f;
                float e = ep[q];
                float z = mp[q] + stdv * e;
                zr[q] = z;
                int d = d0 + q;
                float best = -1e30f;
                float comp[K_MIX];
                #pragma unroll
                for (int k = 0; k < K_MIX; k++) {
                    float tt = (z - mu[d * K_MIX + k]) * isig[d * K_MIX + k];
                    comp[k] = cterm[d * K_MIX + k] - 0.5f * tt * tt;
                    best = fmaxf(best, comp[k]);
                }
                float s2 = 0.f;
                #pragma unroll
                for (int k = 0; k < K_MIX; k++) s2 += __expf(comp[k] - best);
                local += -0.5f * e * e - best - __logf(stdv * s2);
            }
            float4 o4;
            o4.x = (zr[0] > 0.f) ? zr[0] : (__expf(zr[0]) - 1.0f);
            o4.y = (zr[1] > 0.f) ? zr[1] : (__expf(zr[1]) - 1.0f);
            o4.z = (zr[2] > 0.f) ? zr[2] : (__expf(zr[2]) - 1.0f);
            o4.w = (zr[3] > 0.f) ? zr[3] : (__expf(zr[3]) - 1.0f);
            *(float4*)&hout[(size_t)n * D + d0] = o4;
        }
    }
    blockReduceAddTo2(&g_acc[accKl], klv, &g_acc[accIxz], local);
}

// ---------------- final FC ----------------
__global__ void fc_kernel(const float* __restrict__ Wfc, const float* __restrict__ bfc,
                          float* __restrict__ out) {
    int idx = blockIdx.x * blockDim.x + threadIdx.x;
    if (idx >= N_NODES * OUT_C) return;
    int n = idx / OUT_C, o = idx % OUT_C;
    float acc = bfc[o];
    const float* hr = g_h2 + (size_t)n * D2;
    #pragma unroll 8
    for (int d = 0; d < D2; d++) acc += hr[d] * Wfc[d * OUT_C + o];
    out[idx] = acc;
}

__global__ void finalize_kernel(float* out) {
    if (threadIdx.x == 0 && blockIdx.x == 0) {
        double kl  = g_acc[0] / ((double)E_TOT * H1) + g_acc[2] / ((double)E_TOT * H2);
        double ixz = g_acc[1] / (double)N_NODES + g_acc[3] / (double)N_NODES;
        out[N_NODES * OUT_C]     = (float)kl;
        out[N_NODES * OUT_C + 1] = (float)ixz;
    }
}

// ---------------- host orchestration ----------------
static inline int cdiv(long long a, int b) { return (int)((a + b - 1) / b); }

struct Aux {
    cudaStream_t s2;
    cudaEvent_t evFork, evJoin;
    Aux() {
        cudaStreamCreateWithFlags(&s2, cudaStreamNonBlocking);
        cudaEventCreateWithFlags(&evFork, cudaEventDisableTiming);
        cudaEventCreateWithFlags(&evJoin, cudaEventDisableTiming);
    }
};
static Aux& getAux() { static Aux a; return a; }

extern "C" void kernel_launch(void* const* d_in, const int* in_sizes, int n_in,
                              void* d_out, int out_size) {
    const float* x       = (const float*)d_in[0];
    const int*   ei      = (const int*)  d_in[1];
    const float* W1      = (const float*)d_in[2];
    const float* att1    = (const float*)d_in[3];
    const float* pi1     = (const float*)d_in[4];
    const float* mu1     = (const float*)d_in[5];
    const float* logsig1 = (const float*)d_in[6];
    const float* eps1    = (const float*)d_in[7];
    const float* g1      = (const float*)d_in[8];
    const float* W2      = (const float*)d_in[9];
    const float* att2    = (const float*)d_in[10];
    const float* pi2     = (const float*)d_in[11];
    const float* mu2     = (const float*)d_in[12];
    const float* logsig2 = (const float*)d_in[13];
    const float* eps2    = (const float*)d_in[14];
    const float* g2      = (const float*)d_in[15];
    const float* Wfc     = (const float*)d_in[16];
    const float* bfc     = (const float*)d_in[17];
    float* out = (float*)d_out;

    void* p;
    float *xh1, *h1, *xh2, *h2, *si, *sj, *isig1, *cterm1, *isig2, *cterm2;
    cudaGetSymbolAddress(&p, g_xh1);    xh1 = (float*)p;
    cudaGetSymbolAddress(&p, g_h1);     h1 = (float*)p;
    cudaGetSymbolAddress(&p, g_xh2);    xh2 = (float*)p;
    cudaGetSymbolAddress(&p, g_h2);     h2 = (float*)p;
    cudaGetSymbolAddress(&p, g_si);     si = (float*)p;
    cudaGetSymbolAddress(&p, g_sj);     sj = (float*)p;
    cudaGetSymbolAddress(&p, g_isig1);  isig1 = (float*)p;
    cudaGetSymbolAddress(&p, g_cterm1); cterm1 = (float*)p;
    cudaGetSymbolAddress(&p, g_isig2);  isig2 = (float*)p;
    cudaGetSymbolAddress(&p, g_cterm2); cterm2 = (float*)p;

    Aux& aux = getAux();

    // fork side stream: graph setup + MoG precompute, overlapped with GEMM1
    cudaEventRecord(aux.evFork, 0);
    cudaStreamWaitEvent(aux.s2, aux.evFork, 0);
    init_kernel<<<cdiv(N_NODES, 256), 256, 0, aux.s2>>>();
    deg_kernel<<<cdiv(E_TOT, 256), 256, 0, aux.s2>>>(ei);
    scan_kernel<<<1, 1024, 0, aux.s2>>>();
    csrfill_kernel<<<cdiv(E_TOT, 256), 256, 0, aux.s2>>>(ei);
    prep_mog_kernel<<<cdiv(D1 * K_MIX, 256), 256, 0, aux.s2>>>(pi1, logsig1, isig1, cterm1, D1 * K_MIX);
    prep_mog_kernel<<<cdiv(D2 * K_MIX, 256), 256, 0, aux.s2>>>(pi2, logsig2, isig2, cterm2, D2 * K_MIX);
    cudaEventRecord(aux.evJoin, aux.s2);

    // main stream: GEMM1 + scores1 overlap the setup
    {
        dim3 gg(H1 * ON_DIM / 128, cdiv(N_NODES, 128));
        tf32gemm_kernel<<<gg, 256>>>(x, W1, xh1, N_NODES, H1 * ON_DIM, IN_DIM);
    }
    scores_kernel<<<cdiv((long long)N_NODES * H1 * 32, 256), 256>>>(xh1, att1, si, sj, H1);
    cudaStreamWaitEvent(0, aux.evJoin, 0);

    attn_agg_reparam_kernel<<<cdiv(N_NODES * H1, 8), 256>>>(
        xh1, si, sj, g1, eps1, mu1, isig1, cterm1, h1, H1, 0, 1);

    {
        dim3 gg(H2 * ON_DIM / 128, cdiv(N_NODES, 128));
        tf32gemm_kernel<<<gg, 256>>>(h1, W2, xh2, N_NODES, H2 * ON_DIM, D1);
    }
    scores_kernel<<<cdiv((long long)N_NODES * H2 * 32, 256), 256>>>(xh2, att2, si, sj, H2);
    attn_agg_reparam_kernel<<<cdiv(N_NODES * H2, 8), 256>>>(
        xh2, si, sj, g2, eps2, mu2, isig2, cterm2, h2, H2, 2, 3);

    fc_kernel<<<cdiv(N_NODES * OUT_C, 256), 256>>>(Wfc, bfc, out);
    finalize_kernel<<<1, 32>>>(out);
}